// round 13
// baseline (speedup 1.0000x reference)
#include <cuda_runtime.h>
#include <cuda_bf16.h>
#include <cstdint>

// conv_layer_65000035058096 — 3xBF16 mma.sync gather-GEMM (baseline PTX)
// D = xh*wh + xh*wl + xl*wh (bf16 hi/lo split, fp32 accum, err ~2^-18)
// R13: warp tile m32 x n32 (n split across warp pairs) -> 4 warps share each
// B fragment AND 32-reg accumulators -> 3 CTAs/SM (24 warps). CTA = 128 v.

#define V_TOT 163842
#define NCH 28            // k-steps of 16
#define SA 20             // As row stride in words (16 data + 4 pad)

// B fragments, mma m16n8k16 register layout, hi/lo packed:
// g_Bf[(s*8+nb)*32 + lane] = {bh0, bh1, bl0, bl1}
__device__ uint4 g_Bf[NCH * 8 * 32];

__device__ __forceinline__ uint32_t pack_bf16_hi_lo(float hi_elem, float lo_elem) {
    uint32_t r;
    asm("cvt.rn.bf16x2.f32 %0, %1, %2;" : "=r"(r) : "f"(hi_elem), "f"(lo_elem));
    return r;
}

__global__ void pack_B_kernel(const float* __restrict__ W) {
    int idx = blockIdx.x * blockDim.x + threadIdx.x;   // 7168
    if (idx < NCH * 8 * 32) {
        int l = idx & 31, nbk = (idx >> 5) & 7, s = idx >> 8;
        int g = l >> 2, tig = l & 3;
        int o = nbk * 8 + g;
        const float* wr = W + o * 448 + s * 16 + 2 * tig;
        float v[4] = { wr[0], wr[1], wr[8], wr[9] };
        float h[4], lo[4];
#pragma unroll
        for (int i = 0; i < 4; ++i) {
            __nv_bfloat16 hb = __float2bfloat16_rn(v[i]);
            h[i] = __bfloat162float(hb);
            lo[i] = v[i] - h[i];
        }
        uint4 r;
        r.x = pack_bf16_hi_lo(h[1], h[0]);
        r.y = pack_bf16_hi_lo(h[3], h[2]);
        r.z = pack_bf16_hi_lo(lo[1], lo[0]);
        r.w = pack_bf16_hi_lo(lo[3], lo[2]);
        g_Bf[idx] = r;
    }
}

__device__ __forceinline__ void cpa16(uint32_t dst, const void* src) {
    asm volatile("cp.async.cg.shared.global [%0], [%1], 16;" :: "r"(dst), "l"(src) : "memory");
}
__device__ __forceinline__ uint32_t smem_u32(const void* p) {
    uint32_t a;
    asm("{ .reg .u64 t; cvta.to.shared.u64 t, %1; cvt.u32.u64 %0, t; }" : "=r"(a) : "l"(p));
    return a;
}
__device__ __forceinline__ void cvt_pair(float2 p, uint32_t& hi2, uint32_t& lo2) {
    uint32_t h;
    asm("cvt.rn.bf16x2.f32 %0, %1, %2;" : "=r"(h) : "f"(p.y), "f"(p.x));
    float hx = __uint_as_float(h << 16);
    float hy = __uint_as_float(h & 0xFFFF0000u);
    float lx = p.x - hx, ly = p.y - hy;
    uint32_t l;
    asm("cvt.rn.bf16x2.f32 %0, %1, %2;" : "=r"(l) : "f"(ly), "f"(lx));
    hi2 = h; lo2 = l;
}
#define MMA(c, a, b0, b1) asm volatile( \
    "mma.sync.aligned.m16n8k16.row.col.f32.bf16.bf16.f32 " \
    "{%0,%1,%2,%3}, {%4,%5,%6,%7}, {%8,%9}, {%0,%1,%2,%3};" \
    : "+f"((c)[0]), "+f"((c)[1]), "+f"((c)[2]), "+f"((c)[3]) \
    : "r"((a)[0]), "r"((a)[1]), "r"((a)[2]), "r"((a)[3]), "r"(b0), "r"(b1))

__global__ __launch_bounds__(256, 3)
void sconv_bf16(const float* __restrict__ x,
                const int* __restrict__ nb,
                const float* __restrict__ bias,
                float* __restrict__ out) {
    __shared__ float As[2][128 * SA];   // 2 x 10240 B
    __shared__ uint4 Bs[2][8 * 32];     // 2 x 4096 B
    __shared__ int   nbs[896];          // [j][row]

    const int t    = threadIdx.x;
    const int lane = t & 31;
    const int w    = t >> 5;
    const int g    = lane >> 2;
    const int tig  = lane & 3;
    const int rg   = w >> 1;            // row group 0..3 (32 rows each)
    const int nh   = w & 1;             // n-half 0..1 (32 outputs)
    const int wv   = rg << 5;           // warp vertex base
    const int batch = blockIdx.y;
    const int v0    = blockIdx.x * 128;
    const long long xbase = (long long)batch * V_TOT;

    // ---- stage neighbor indices: nbs[j*128 + r]
#pragma unroll
    for (int i = 0; i < 4; ++i) {
        int idx = t + (i << 8);
        if (idx < 896) {
            int r = idx & 127, j = idx >> 7;
            int vv = v0 + r; if (vv >= V_TOT) vv = V_TOT - 1;
            nbs[idx] = nb[vv * 7 + j];
        }
    }
    __syncthreads();

    uint32_t asb[2] = { smem_u32(&As[0][0]), smem_u32(&As[1][0]) };
    uint32_t bsb[2] = { smem_u32(&Bs[0][0]), smem_u32(&Bs[1][0]) };

    // acc[rb][nblk][e]: rows wv+16rb.., outputs (nh*4+nblk)*8..
    float acc[2][4][4];
#pragma unroll
    for (int rb = 0; rb < 2; ++rb)
#pragma unroll
        for (int n = 0; n < 4; ++n)
#pragma unroll
            for (int e = 0; e < 4; ++e) acc[rb][n][e] = 0.0f;

    // staging mapping: 512 (row,quad) tasks over 256 threads x 2
    const int rS  = t >> 1;
    const int qS0 = (t & 1) << 1;

    // prologue: stage chunk 0
    {
#pragma unroll
        for (int i = 0; i < 2; ++i) {
            int q = qS0 + i;
            cpa16(asb[0] + (rS * SA + (q << 2)) * 4,
                  x + ((xbase + nbs[rS]) << 6) + (q << 2));
        }
        cpa16(bsb[0] + t * 16, (const char*)g_Bf + t * 16);
        asm volatile("cp.async.commit_group;" ::: "memory");
    }

    for (int c = 0; c < NCH; ++c) {
        const int buf = c & 1;

        if (c + 1 < NCH) {
            const int cn = c + 1;
            const int j  = cn >> 2;
            const int kb = (cn & 3) << 4;
            const int bn = cn & 1;
            const int row = nbs[j * 128 + rS];
#pragma unroll
            for (int i = 0; i < 2; ++i) {
                int q = qS0 + i;
                cpa16(asb[bn] + (rS * SA + (q << 2)) * 4,
                      x + ((xbase + row) << 6) + kb + (q << 2));
            }
            cpa16(bsb[bn] + t * 16, (const char*)g_Bf + cn * 4096 + t * 16);
            asm volatile("cp.async.commit_group;" ::: "memory");
            asm volatile("cp.async.wait_group 1;" ::: "memory");
        } else {
            asm volatile("cp.async.wait_group 0;" ::: "memory");
        }
        __syncthreads();

        // ---- compute chunk c: two 16-row blocks share the 4 B fragments
        const float* aB = &As[buf][0];
        uint32_t ah[2][4], al[2][4];
#pragma unroll
        for (int rb = 0; rb < 2; ++rb) {
            const int r0 = (wv + (rb << 4) + g) * SA;
            const int r1 = r0 + 8 * SA;
            float2 p00 = *reinterpret_cast<const float2*>(aB + r0 + 2 * tig);
            float2 p10 = *reinterpret_cast<const float2*>(aB + r1 + 2 * tig);
            float2 p01 = *reinterpret_cast<const float2*>(aB + r0 + 2 * tig + 8);
            float2 p11 = *reinterpret_cast<const float2*>(aB + r1 + 2 * tig + 8);
            cvt_pair(p00, ah[rb][0], al[rb][0]);
            cvt_pair(p10, ah[rb][1], al[rb][1]);
            cvt_pair(p01, ah[rb][2], al[rb][2]);
            cvt_pair(p11, ah[rb][3], al[rb][3]);
        }

        const uint4* bB = &Bs[buf][0];
#pragma unroll
        for (int nblk = 0; nblk < 4; ++nblk) {
            uint4 bf = bB[(((nh << 2) + nblk) << 5) + lane];
            MMA(acc[0][nblk], ah[0], bf.x, bf.y);
            MMA(acc[1][nblk], ah[1], bf.x, bf.y);
            MMA(acc[0][nblk], ah[0], bf.z, bf.w);
            MMA(acc[1][nblk], ah[1], bf.z, bf.w);
            MMA(acc[0][nblk], al[0], bf.x, bf.y);
            MMA(acc[1][nblk], al[1], bf.x, bf.y);
        }
        __syncthreads();   // done reading buf before it is re-staged
    }

    // ---- epilogue: D frags -> global (+bias)
#pragma unroll
    for (int rb = 0; rb < 2; ++rb) {
        const int vr0 = v0 + wv + (rb << 4) + g;
        const int vr1 = vr0 + 8;
#pragma unroll
        for (int nblk = 0; nblk < 4; ++nblk) {
            const int n = (((nh << 2) + nblk) << 3) + 2 * tig;
            const float2 b2 = *reinterpret_cast<const float2*>(bias + n);
            if (vr0 < V_TOT)
                *reinterpret_cast<float2*>(out + ((xbase + vr0) << 6) + n) =
                    make_float2(acc[rb][nblk][0] + b2.x, acc[rb][nblk][1] + b2.y);
            if (vr1 < V_TOT)
                *reinterpret_cast<float2*>(out + ((xbase + vr1) << 6) + n) =
                    make_float2(acc[rb][nblk][2] + b2.x, acc[rb][nblk][3] + b2.y);
        }
    }
}

extern "C" void kernel_launch(void* const* d_in, const int* in_sizes, int n_in,
                              void* d_out, int out_size) {
    const float* x   = (const float*)d_in[0];   // (2, V, 64) f32
    const int*   nbi = (const int*)d_in[1];     // (V*7,) i32
    const float* W   = (const float*)d_in[2];   // (64, 448) f32
    const float* b   = (const float*)d_in[3];   // (64,) f32
    float*       out = (float*)d_out;           // (2, V, 64) f32

    pack_B_kernel<<<(NCH * 8 * 32 + 255) / 256, 256>>>(W);

    dim3 grid((V_TOT + 127) / 128, 2);
    sconv_bf16<<<grid, 256>>>(x, nbi, b, out);
}

// round 14
// speedup vs baseline: 1.0854x; 1.0854x over previous
#include <cuda_runtime.h>
#include <cuda_bf16.h>
#include <cstdint>

// conv_layer_65000035058096 — 3xBF16 mma.sync gather-GEMM (baseline PTX)
// D = xh*wh + xh*wl + xl*wh (bf16 hi/lo split, fp32 accum, err ~2^-18)
// R14: R12 shape (warp m32 x n64, CTA 256 v) but FULLY DESYNCHRONIZED:
// B frags via LDG (L1-broadcast), per-warp A staging with per-thread cp.async
// groups -> no __syncthreads in the main loop; warps pipeline independently.

#define V_TOT 163842
#define NCH 28            // k-steps of 16
#define SA 20             // As row stride in words (16 data + 4 pad)
#define TILE_V 256

// B fragments, mma m16n8k16 register layout, hi/lo packed:
// g_Bf[(s*8+nb)*32 + lane] = {bh0, bh1, bl0, bl1}
__device__ uint4 g_Bf[NCH * 8 * 32];

__device__ __forceinline__ uint32_t pack_bf16_hi_lo(float hi_elem, float lo_elem) {
    uint32_t r;
    asm("cvt.rn.bf16x2.f32 %0, %1, %2;" : "=r"(r) : "f"(hi_elem), "f"(lo_elem));
    return r;
}

__global__ void pack_B_kernel(const float* __restrict__ W) {
    int idx = blockIdx.x * blockDim.x + threadIdx.x;   // 7168
    if (idx < NCH * 8 * 32) {
        int l = idx & 31, nbk = (idx >> 5) & 7, s = idx >> 8;
        int g = l >> 2, tig = l & 3;
        int o = nbk * 8 + g;
        const float* wr = W + o * 448 + s * 16 + 2 * tig;
        float v[4] = { wr[0], wr[1], wr[8], wr[9] };
        float h[4], lo[4];
#pragma unroll
        for (int i = 0; i < 4; ++i) {
            __nv_bfloat16 hb = __float2bfloat16_rn(v[i]);
            h[i] = __bfloat162float(hb);
            lo[i] = v[i] - h[i];
        }
        uint4 r;
        r.x = pack_bf16_hi_lo(h[1], h[0]);
        r.y = pack_bf16_hi_lo(h[3], h[2]);
        r.z = pack_bf16_hi_lo(lo[1], lo[0]);
        r.w = pack_bf16_hi_lo(lo[3], lo[2]);
        g_Bf[idx] = r;
    }
}

__device__ __forceinline__ void cpa16(uint32_t dst, const void* src) {
    asm volatile("cp.async.cg.shared.global [%0], [%1], 16;" :: "r"(dst), "l"(src) : "memory");
}
__device__ __forceinline__ uint32_t smem_u32(const void* p) {
    uint32_t a;
    asm("{ .reg .u64 t; cvta.to.shared.u64 t, %1; cvt.u32.u64 %0, t; }" : "=r"(a) : "l"(p));
    return a;
}
__device__ __forceinline__ void cvt_pair(float2 p, uint32_t& hi2, uint32_t& lo2) {
    uint32_t h;
    asm("cvt.rn.bf16x2.f32 %0, %1, %2;" : "=r"(h) : "f"(p.y), "f"(p.x));
    float hx = __uint_as_float(h << 16);
    float hy = __uint_as_float(h & 0xFFFF0000u);
    float lx = p.x - hx, ly = p.y - hy;
    uint32_t l;
    asm("cvt.rn.bf16x2.f32 %0, %1, %2;" : "=r"(l) : "f"(ly), "f"(lx));
    hi2 = h; lo2 = l;
}
#define MMA(c, a, b0, b1) asm volatile( \
    "mma.sync.aligned.m16n8k16.row.col.f32.bf16.bf16.f32 " \
    "{%0,%1,%2,%3}, {%4,%5,%6,%7}, {%8,%9}, {%0,%1,%2,%3};" \
    : "+f"((c)[0]), "+f"((c)[1]), "+f"((c)[2]), "+f"((c)[3]) \
    : "r"((a)[0]), "r"((a)[1]), "r"((a)[2]), "r"((a)[3]), "r"(b0), "r"(b1))

__global__ __launch_bounds__(256, 2)
void sconv_bf16(const float* __restrict__ x,
                const int* __restrict__ nb,
                const float* __restrict__ bias,
                float* __restrict__ out) {
    __shared__ float As[2][TILE_V * SA];   // 2 x 20480 B; warp w owns rows [32w,32w+32)
    __shared__ int   nbs[7 * TILE_V];      // 7168 B

    const int t    = threadIdx.x;
    const int lane = t & 31;
    const int w    = t >> 5;
    const int g    = lane >> 2;
    const int tig  = lane & 3;
    const int wv   = w << 5;            // warp vertex base (32 rows, exclusive)
    const int batch = blockIdx.y;
    const int v0    = blockIdx.x * TILE_V;
    const long long xbase = (long long)batch * V_TOT;

    // ---- stage neighbor indices: nbs[j*256 + r]  (ONLY CTA-wide barrier)
#pragma unroll
    for (int i = 0; i < 7; ++i) {
        int idx = t + (i << 8);
        int r = idx & 255, j = idx >> 8;
        int vv = v0 + r; if (vv >= V_TOT) vv = V_TOT - 1;
        nbs[idx] = nb[vv * 7 + j];
    }
    __syncthreads();

    uint32_t asb[2] = { smem_u32(&As[0][0]), smem_u32(&As[1][0]) };

    // acc[rb][nblk][e]: rows wv+16rb.., outputs nblk*8..
    float acc[2][8][4];
#pragma unroll
    for (int rb = 0; rb < 2; ++rb)
#pragma unroll
        for (int n = 0; n < 8; ++n)
#pragma unroll
            for (int e = 0; e < 4; ++e) acc[rb][n][e] = 0.0f;

    // per-warp staging: lane stages its own row (wv+lane? no: 32 rows, 1/lane)
    const int rMine = wv + lane;           // CTA-local row this lane stages

    // prologue: stage chunk 0 (j=0, kb=0): 4 x 16B per lane
    {
        const float* src = x + ((xbase + nbs[rMine]) << 6);
        const uint32_t dst = asb[0] + rMine * SA * 4;
#pragma unroll
        for (int q = 0; q < 4; ++q)
            cpa16(dst + (q << 4), src + (q << 2));
        asm volatile("cp.async.commit_group;" ::: "memory");
    }

    for (int c = 0; c < NCH; ++c) {
        const int buf = c & 1;

        // stage chunk c+1 into the other buffer (per-warp rows only)
        if (c + 1 < NCH) {
            const int cn = c + 1;
            const int j  = cn >> 2;
            const int kb = (cn & 3) << 4;
            const float* src = x + ((xbase + nbs[j * 256 + rMine]) << 6) + kb;
            const uint32_t dst = asb[cn & 1] + rMine * SA * 4;
#pragma unroll
            for (int q = 0; q < 4; ++q)
                cpa16(dst + (q << 4), src + (q << 2));
            asm volatile("cp.async.commit_group;" ::: "memory");
            asm volatile("cp.async.wait_group 1;" ::: "memory");
        } else {
            asm volatile("cp.async.wait_group 0;" ::: "memory");
        }
        __syncwarp();   // warp-local visibility of its 32 staged rows

        // ---- compute chunk c (warp-private rows; B frags via LDG, L1-hot)
        const float* aB = &As[buf][0];
        uint32_t ah[2][4], al[2][4];
#pragma unroll
        for (int rb = 0; rb < 2; ++rb) {
            const int r0 = (wv + (rb << 4) + g) * SA;
            const int r1 = r0 + 8 * SA;
            float2 p00 = *reinterpret_cast<const float2*>(aB + r0 + 2 * tig);
            float2 p10 = *reinterpret_cast<const float2*>(aB + r1 + 2 * tig);
            float2 p01 = *reinterpret_cast<const float2*>(aB + r0 + 2 * tig + 8);
            float2 p11 = *reinterpret_cast<const float2*>(aB + r1 + 2 * tig + 8);
            cvt_pair(p00, ah[rb][0], al[rb][0]);
            cvt_pair(p10, ah[rb][1], al[rb][1]);
            cvt_pair(p01, ah[rb][2], al[rb][2]);
            cvt_pair(p11, ah[rb][3], al[rb][3]);
        }

        const uint4* bG = g_Bf + (c << 8) + lane;
#pragma unroll
        for (int nblk = 0; nblk < 8; ++nblk) {
            uint4 bf = bG[nblk << 5];      // LDG.128, L1 broadcast across warps
            MMA(acc[0][nblk], ah[0], bf.x, bf.y);
            MMA(acc[1][nblk], ah[1], bf.x, bf.y);
            MMA(acc[0][nblk], ah[0], bf.z, bf.w);
            MMA(acc[1][nblk], ah[1], bf.z, bf.w);
            MMA(acc[0][nblk], al[0], bf.x, bf.y);
            MMA(acc[1][nblk], al[1], bf.x, bf.y);
        }
        __syncwarp();   // all lanes done reading buf before re-staging it
    }

    // ---- epilogue: D frags -> global (+bias); warp-private rows, no sync
#pragma unroll
    for (int rb = 0; rb < 2; ++rb) {
        const int vr0 = v0 + wv + (rb << 4) + g;
        const int vr1 = vr0 + 8;
#pragma unroll
        for (int nblk = 0; nblk < 8; ++nblk) {
            const int n = (nblk << 3) + 2 * tig;
            const float2 b2 = *reinterpret_cast<const float2*>(bias + n);
            if (vr0 < V_TOT)
                *reinterpret_cast<float2*>(out + ((xbase + vr0) << 6) + n) =
                    make_float2(acc[rb][nblk][0] + b2.x, acc[rb][nblk][1] + b2.y);
            if (vr1 < V_TOT)
                *reinterpret_cast<float2*>(out + ((xbase + vr1) << 6) + n) =
                    make_float2(acc[rb][nblk][2] + b2.x, acc[rb][nblk][3] + b2.y);
        }
    }
}

extern "C" void kernel_launch(void* const* d_in, const int* in_sizes, int n_in,
                              void* d_out, int out_size) {
    const float* x   = (const float*)d_in[0];   // (2, V, 64) f32
    const int*   nbi = (const int*)d_in[1];     // (V*7,) i32
    const float* W   = (const float*)d_in[2];   // (64, 448) f32
    const float* b   = (const float*)d_in[3];   // (64,) f32
    float*       out = (float*)d_out;           // (2, V, 64) f32

    pack_B_kernel<<<(NCH * 8 * 32 + 255) / 256, 256>>>(W);

    dim3 grid((V_TOT + TILE_V - 1) / TILE_V, 2);
    sconv_bf16<<<grid, 256>>>(x, nbi, b, out);
}